// round 12
// baseline (speedup 1.0000x reference)
#include <cuda_runtime.h>
#include <cuda_bf16.h>
#include <cstdint>
#include <cstddef>

#define TT 1024
#define BB 64
#define DD 512
#define HH 512

// Recurrence partition: NI batch-groups (clusters) x NJ hidden-slices
#define NI 16
#define NJ 8
#define BSL (BB / NI)        // 4 batch rows per group
#define HSL (HH / NJ)        // 64 hidden units per slice
#define RKC 8                // k-chunks of 64 (one per 64-thread group == one slice)
#define RTHREADS 512
#define SLICE_BYTES (BSL * HSL * 4)
#define HS_BYTES (NJ * SLICE_BYTES)

// Device scratch (no cudaMalloc allowed)
__device__ float g_Z [(size_t)TT * BB * HH];
__device__ __nv_bfloat16 g_Ahi[(size_t)TT * BB * DD];
__device__ __nv_bfloat16 g_Alo[(size_t)TT * BB * DD];
__device__ __nv_bfloat16 g_Whi[(size_t)HH * DD];
__device__ __nv_bfloat16 g_Wlo[(size_t)HH * DD];

// ---------------------------------------------------------------------------
// PTX helpers
// ---------------------------------------------------------------------------
__device__ __forceinline__ uint32_t smem_u32(const void* p) {
    uint32_t a;
    asm("{ .reg .u64 t; cvta.to.shared.u64 t, %1; cvt.u32.u64 %0, t; }"
        : "=r"(a) : "l"(p));
    return a;
}
__device__ __forceinline__ uint32_t mapa_u32(uint32_t addr, uint32_t rank) {
    uint32_t r;
    asm("mapa.shared::cluster.u32 %0, %1, %2;" : "=r"(r) : "r"(addr), "r"(rank));
    return r;
}
__device__ __forceinline__ void mbar_init(uint32_t mbar, uint32_t cnt) {
    asm volatile("mbarrier.init.shared.b64 [%0], %1;" :: "r"(mbar), "r"(cnt) : "memory");
}
__device__ __forceinline__ void mbar_arrive_expect_tx(uint32_t mbar, uint32_t tx) {
    asm volatile("mbarrier.arrive.expect_tx.shared.b64 _, [%0], %1;"
                 :: "r"(mbar), "r"(tx) : "memory");
}
__device__ __forceinline__ void mbar_wait_parity(uint32_t mbar, uint32_t parity) {
    asm volatile(
        "{\n\t"
        ".reg .pred P;\n\t"
        "WAIT_%=:\n\t"
        "mbarrier.try_wait.parity.acquire.cta.shared::cta.b64 P, [%0], %1, 0x989680;\n\t"
        "@P bra.uni DONE_%=;\n\t"
        "bra.uni WAIT_%=;\n\t"
        "DONE_%=:\n\t"
        "}"
        :: "r"(mbar), "r"(parity) : "memory");
}
__device__ __forceinline__ void bulk_dsmem(uint32_t dst_cluster, uint32_t src_cta,
                                           uint32_t bytes, uint32_t mbar_cluster) {
    asm volatile(
        "cp.async.bulk.shared::cluster.shared::cta.mbarrier::complete_tx::bytes "
        "[%0], [%1], %2, [%3];"
        :: "r"(dst_cluster), "r"(src_cta), "r"(bytes), "r"(mbar_cluster) : "memory");
}
__device__ __forceinline__ void fence_proxy_async_cta() {
    asm volatile("fence.proxy.async.shared::cta;" ::: "memory");
}
__device__ __forceinline__ void ffma2(unsigned long long& d,
                                      unsigned long long a, unsigned long long b) {
    asm("fma.rn.f32x2 %0, %1, %2, %0;" : "+l"(d) : "l"(a), "l"(b));
}
__device__ __forceinline__ unsigned long long pack_f2(float lo, float hi) {
    return (unsigned long long)__float_as_uint(lo) |
           ((unsigned long long)__float_as_uint(hi) << 32);
}
__device__ __forceinline__ float lo_f(unsigned long long v) {
    return __uint_as_float((unsigned int)v);
}
__device__ __forceinline__ float hi_f(unsigned long long v) {
    return __uint_as_float((unsigned int)(v >> 32));
}

// mma.sync m16n8k16 bf16 (sm_80+ baseline PTX: safe at compute_103)
__device__ __forceinline__ void mma16816(float* d, const uint32_t* a, const uint32_t* b) {
    asm volatile(
        "mma.sync.aligned.m16n8k16.row.col.f32.bf16.bf16.f32 "
        "{%0,%1,%2,%3}, {%4,%5,%6,%7}, {%8,%9}, {%0,%1,%2,%3};"
        : "+f"(d[0]), "+f"(d[1]), "+f"(d[2]), "+f"(d[3])
        : "r"(a[0]), "r"(a[1]), "r"(a[2]), "r"(a[3]), "r"(b[0]), "r"(b[1]));
}
__device__ __forceinline__ void ldsm_x4(uint32_t* r, uint32_t addr) {
    asm volatile("ldmatrix.sync.aligned.m8n8.x4.shared.b16 {%0,%1,%2,%3}, [%4];"
        : "=r"(r[0]), "=r"(r[1]), "=r"(r[2]), "=r"(r[3]) : "r"(addr));
}

// ---------------------------------------------------------------------------
// Split-bf16 conversion (weights only)
// ---------------------------------------------------------------------------
__global__ void split_kernel(const float* __restrict__ src,
                             __nv_bfloat16* __restrict__ hi,
                             __nv_bfloat16* __restrict__ lo, int n)
{
    int idx = blockIdx.x * blockDim.x + threadIdx.x;
    int stride = gridDim.x * blockDim.x;
    for (int i = idx; i < n; i += stride) {
        float x = src[i];
        __nv_bfloat16 h = __float2bfloat16(x);
        hi[i] = h;
        lo[i] = __float2bfloat16(x - __bfloat162float(h));
    }
}

// ---------------------------------------------------------------------------
// HMMA GEMM (unchanged from R10 passing version)
// ---------------------------------------------------------------------------
#define KB 32
#define PAD 40

__global__ __launch_bounds__(256) void mma_gemm_kernel(
    const float* __restrict__ Af32,
    const __nv_bfloat16* __restrict__ Ahi, const __nv_bfloat16* __restrict__ Alo,
    const __nv_bfloat16* __restrict__ Whi, const __nv_bfloat16* __restrict__ Wlo,
    const float* __restrict__ b1, const float* __restrict__ b2,
    float* __restrict__ C)
{
    __shared__ __nv_bfloat16 sAh[128][PAD];
    __shared__ __nv_bfloat16 sAl[128][PAD];
    __shared__ __nv_bfloat16 sWh[128][PAD];
    __shared__ __nv_bfloat16 sWl[128][PAD];

    const int tid   = threadIdx.x;
    const int wid   = tid >> 5;
    const int lane  = tid & 31;
    const int m0    = blockIdx.x * 128;
    const int n0    = blockIdx.y * 128;
    const int wm    = (wid >> 2) * 64;
    const int wn    = (wid & 3) * 32;

    float acc[4][4][4];
#pragma unroll
    for (int i = 0; i < 4; i++)
#pragma unroll
        for (int j = 0; j < 4; j++)
#pragma unroll
            for (int r = 0; r < 4; r++) acc[i][j][r] = 0.0f;

    const int ar = lane & 15, ac = (lane >> 4) * 8;
    const int br = (lane & 7) + ((lane >> 4) << 3), bc = ((lane >> 3) & 1) * 8;

    for (int kb = 0; kb < DD / KB; kb++) {
        const int k0 = kb * KB;

        // ---- A tiles ----
        if (Af32) {
#pragma unroll
            for (int it = 0; it < 4; it++) {
                int idx = it * 256 + tid;
                int r   = idx >> 3;
                int c4  = (idx & 7) * 4;
                float4 v = *(const float4*)(Af32 + (size_t)(m0 + r) * DD + k0 + c4);
                __nv_bfloat16 hx = __float2bfloat16(v.x);
                __nv_bfloat16 hy = __float2bfloat16(v.y);
                __nv_bfloat16 hz = __float2bfloat16(v.z);
                __nv_bfloat16 hw = __float2bfloat16(v.w);
                *(__nv_bfloat162*)&sAh[r][c4]     = __nv_bfloat162(hx, hy);
                *(__nv_bfloat162*)&sAh[r][c4 + 2] = __nv_bfloat162(hz, hw);
                __nv_bfloat162 l0, l1;
                l0.x = __float2bfloat16(v.x - __bfloat162float(hx));
                l0.y = __float2bfloat16(v.y - __bfloat162float(hy));
                l1.x = __float2bfloat16(v.z - __bfloat162float(hz));
                l1.y = __float2bfloat16(v.w - __bfloat162float(hw));
                *(__nv_bfloat162*)&sAl[r][c4]     = l0;
                *(__nv_bfloat162*)&sAl[r][c4 + 2] = l1;
            }
        } else {
#pragma unroll
            for (int tile = 0; tile < 2; tile++) {
                const __nv_bfloat16* src = (tile == 0) ? Ahi : Alo;
                __nv_bfloat16 (*dst)[PAD] = (tile == 0) ? sAh : sAl;
#pragma unroll
                for (int it = 0; it < 2; it++) {
                    int idx = it * 256 + tid;
                    int r   = idx >> 2;
                    int c   = (idx & 3) * 8;
                    uint4 v = *(const uint4*)(src + (size_t)(m0 + r) * DD + k0 + c);
                    *(uint4*)&dst[r][c] = v;
                }
            }
        }

        // ---- W tiles ----
#pragma unroll
        for (int tile = 0; tile < 2; tile++) {
            const __nv_bfloat16* src = (tile == 0) ? Whi : Wlo;
            __nv_bfloat16 (*dst)[PAD] = (tile == 0) ? sWh : sWl;
#pragma unroll
            for (int it = 0; it < 2; it++) {
                int idx = it * 256 + tid;
                int r   = idx >> 2;
                int c   = (idx & 3) * 8;
                uint4 v = *(const uint4*)(src + (size_t)(n0 + r) * DD + k0 + c);
                *(uint4*)&dst[r][c] = v;
            }
        }
        __syncthreads();

#pragma unroll
        for (int ks = 0; ks < 2; ks++) {
            const int kk = ks * 16;
            uint32_t fAh[4][4], fAl[4][4], fWh[2][4], fWl[2][4];
#pragma unroll
            for (int mf = 0; mf < 4; mf++) {
                ldsm_x4(fAh[mf], smem_u32(&sAh[wm + mf * 16 + ar][kk + ac]));
                ldsm_x4(fAl[mf], smem_u32(&sAl[wm + mf * 16 + ar][kk + ac]));
            }
#pragma unroll
            for (int np = 0; np < 2; np++) {
                ldsm_x4(fWh[np], smem_u32(&sWh[wn + np * 16 + br][kk + bc]));
                ldsm_x4(fWl[np], smem_u32(&sWl[wn + np * 16 + br][kk + bc]));
            }
#pragma unroll
            for (int mf = 0; mf < 4; mf++) {
#pragma unroll
                for (int np = 0; np < 2; np++) {
#pragma unroll
                    for (int h = 0; h < 2; h++) {
                        const int nf = np * 2 + h;
                        mma16816(acc[mf][nf], fAh[mf], &fWh[np][h * 2]);
                        mma16816(acc[mf][nf], fAh[mf], &fWl[np][h * 2]);
                        mma16816(acc[mf][nf], fAl[mf], &fWh[np][h * 2]);
                    }
                }
            }
        }
        __syncthreads();
    }

    const int erow = lane >> 2;
    const int ecol = (lane & 3) * 2;
#pragma unroll
    for (int mf = 0; mf < 4; mf++) {
#pragma unroll
        for (int nf = 0; nf < 4; nf++) {
            const int n = n0 + wn + nf * 8 + ecol;
            const float bv0 = __ldg(b1 + n)     + __ldg(b2 + n);
            const float bv1 = __ldg(b1 + n + 1) + __ldg(b2 + n + 1);
            const int r0 = m0 + wm + mf * 16 + erow;
            float2 o0 = make_float2(acc[mf][nf][0] + bv0, acc[mf][nf][1] + bv1);
            float2 o1 = make_float2(acc[mf][nf][2] + bv0, acc[mf][nf][3] + bv1);
            *(float2*)(C + (size_t)r0 * HH + n)       = o0;
            *(float2*)(C + (size_t)(r0 + 8) * HH + n) = o1;
        }
    }
}

// ---------------------------------------------------------------------------
// Persistent recurrence kernel v5: 512 threads, 8 k-chunks of 64.
// Thread group kc (64 threads = 2 warps) consumes exactly slice kc of h:
// ONE mbarrier wait per thread per step, and 16 warps/CTA double the
// eligible-warp pool (issue% was ~33% with 8 warps).
// Epilogue (tid < 256) writes fp32 Y or split-bf16 (Yhi/Ylo).
// ---------------------------------------------------------------------------
__global__ __launch_bounds__(RTHREADS, 1) __cluster_dims__(NJ, 1, 1)
void recur_kernel(
    const float* __restrict__ Z, const float* __restrict__ Whh,
    float* __restrict__ Yf,
    __nv_bfloat16* __restrict__ Yhi, __nv_bfloat16* __restrict__ Ylo)
{
    __shared__ float hs[2][NJ][BSL][HSL];        // 16 KB double-buffered h
    __shared__ float red[BSL][RKC][HSL];         // 8 KB partial sums
    __shared__ float stage[2][BSL][HSL];         // 2 KB staging
    __shared__ alignas(8) unsigned long long mbar[2][NJ];

    const int j    = blockIdx.x;                 // hidden slice = cluster rank
    const int i    = blockIdx.y;                 // batch group
    const int tid  = threadIdx.x;
    const int kc   = tid >> 6;                   // 0..7: k-chunk == source slice
    const int jloc = tid & 63;                   // hidden idx within my slice
    const int b0   = i * BSL;

    const uint32_t hs_base    = smem_u32(&hs[0][0][0][0]);
    const uint32_t mbar_base  = smem_u32(&mbar[0][0]);
    const uint32_t stage_base = smem_u32(&stage[0][0][0]);

    if (tid == 0) {
#pragma unroll
        for (int ph = 0; ph < 2; ph++)
#pragma unroll
            for (int s = 0; s < NJ; s++) {
                const uint32_t mb = mbar_base + (uint32_t)(ph * NJ + s) * 8;
                mbar_init(mb, 1);
                mbar_arrive_expect_tx(mb, SLICE_BYTES);
            }
    }
    asm volatile("barrier.cluster.arrive.aligned;" ::: "memory");
    asm volatile("barrier.cluster.wait.aligned;"  ::: "memory");

    uint32_t my_peer_hs = 0, my_peer_mb = 0;
    if (tid < NJ) {
        my_peer_hs = mapa_u32(hs_base,   (uint32_t)tid);
        my_peer_mb = mapa_u32(mbar_base, (uint32_t)tid);
    }

    // My Whh chunk: rows j*64+jloc, k in [kc*64, kc*64+64), packed pairs.
    unsigned long long w2[32];
    {
        const float* wrow = Whh + (size_t)(j * HSL + jloc) * HH + kc * 64;
#pragma unroll
        for (int q = 0; q < 16; q++) {
            float4 v = *(const float4*)(wrow + q * 4);
            w2[q * 2 + 0] = pack_f2(v.x, v.y);
            w2[q * 2 + 1] = pack_f2(v.z, v.w);
        }
    }

    // Output mapping: threads 0..255 own the BSL*HSL = 256 outputs.
    const int rb  = (tid >> 6) & 3;
    const int rjj = tid & 63;
    const int brow = b0 + rb;
    const int jg   = j * HSL + rjj;
    const size_t zy_off = (size_t)brow * HH + jg;

    // My single slice barrier per phase
    const uint32_t mbP0 = mbar_base + (uint32_t)(0 * NJ + kc) * 8;
    const uint32_t mbP1 = mbar_base + (uint32_t)(1 * NJ + kc) * 8;

    int par[2] = {0, 0};

    for (int t = 0; t < TT; t++) {
        const int ph = t & 1;

        float zv = (tid < 256) ? __ldcs(Z + (size_t)t * BB * HH + zy_off) : 0.0f;

        float acc = 0.0f;
        if (t > 0) {
            const uint32_t mb = (ph == 0) ? mbP0 : mbP1;
            const int p = par[ph];

            // Wait ONLY for my slice's 512B delivery
            mbar_wait_parity(mb, p);
            if (jloc == 0) mbar_arrive_expect_tx(mb, SLICE_BYTES);  // re-arm
            par[ph] = p ^ 1;

            unsigned long long acc2[BSL];
#pragma unroll
            for (int b = 0; b < BSL; b++) acc2[b] = pack_f2(0.0f, 0.0f);
#pragma unroll
            for (int b = 0; b < BSL; b++) {
                const ulonglong2* hp = (const ulonglong2*)&hs[ph][kc][b][0];
#pragma unroll
                for (int q = 0; q < 16; q++) {
                    ulonglong2 hv = hp[q];
                    ffma2(acc2[b], hv.x, w2[q * 2 + 0]);
                    ffma2(acc2[b], hv.y, w2[q * 2 + 1]);
                }
            }
#pragma unroll
            for (int b = 0; b < BSL; b++)
                red[b][kc][jloc] = lo_f(acc2[b]) + hi_f(acc2[b]);
            __syncthreads();

            if (tid < 256) {
#pragma unroll
                for (int c = 0; c < RKC; c++) acc += red[rb][c][rjj];
            }
        }

        // tanh + output + stage (threads 0..255)
        if (tid < 256) {
            float val = tanhf(acc + zv);
            const size_t go = (size_t)t * BB * HH + zy_off;
            if (Yhi) {
                __nv_bfloat16 h = __float2bfloat16(val);
                Yhi[go] = h;
                Ylo[go] = __float2bfloat16(val - __bfloat162float(h));
            } else {
                Yf[go] = val;
            }
            stage[t & 1][rb][rjj] = val;
        }
        __syncthreads();

        if (t + 1 < TT && tid < NJ) {
            fence_proxy_async_cta();
            const uint32_t src = stage_base + (uint32_t)(t & 1) * SLICE_BYTES;
            const uint32_t dst = my_peer_hs
                + (uint32_t)(ph ^ 1) * HS_BYTES + (uint32_t)j * SLICE_BYTES;
            const uint32_t mb  = my_peer_mb + (uint32_t)((ph ^ 1) * NJ + j) * 8;
            bulk_dsmem(dst, src, SLICE_BYTES, mb);
        }
    }

    asm volatile("barrier.cluster.arrive.aligned;" ::: "memory");
    asm volatile("barrier.cluster.wait.aligned;"  ::: "memory");
}

// ---------------------------------------------------------------------------
extern "C" void kernel_launch(void* const* d_in, const int* in_sizes, int n_in,
                              void* d_out, int out_size)
{
    const float* Xt   = (const float*)d_in[0];
    const float* ihW0 = (const float*)d_in[1];
    const float* ihB0 = (const float*)d_in[2];
    const float* hhW0 = (const float*)d_in[3];
    const float* hhB0 = (const float*)d_in[4];
    const float* ihW1 = (const float*)d_in[5];
    const float* ihB1 = (const float*)d_in[6];
    const float* hhW1 = (const float*)d_in[7];
    const float* hhB1 = (const float*)d_in[8];
    float* out = (float*)d_out;

    float *zp = nullptr;
    __nv_bfloat16 *ahi, *alo, *whi, *wlo;
    cudaGetSymbolAddress((void**)&zp,  g_Z);
    cudaGetSymbolAddress((void**)&ahi, g_Ahi);
    cudaGetSymbolAddress((void**)&alo, g_Alo);
    cudaGetSymbolAddress((void**)&whi, g_Whi);
    cudaGetSymbolAddress((void**)&wlo, g_Wlo);

    dim3 ggrid(TT * BB / 128, HH / 128);   // (512, 4)
    dim3 rgrid(NJ, NI);                    // (8, 16)

    const int NW = HH * DD;

    // ---- Layer 0 ----
    split_kernel<<<512, 256>>>(ihW0, whi, wlo, NW);
    mma_gemm_kernel<<<ggrid, 256>>>(Xt, nullptr, nullptr, whi, wlo, ihB0, hhB0, zp);
    recur_kernel<<<rgrid, RTHREADS>>>(zp, hhW0, nullptr, ahi, alo);

    // ---- Layer 1 ----
    split_kernel<<<512, 256>>>(ihW1, whi, wlo, NW);
    mma_gemm_kernel<<<ggrid, 256>>>(nullptr, ahi, alo, whi, wlo, ihB1, hhB1, zp);
    recur_kernel<<<rgrid, RTHREADS>>>(zp, hhW1, out, nullptr, nullptr);
}

// round 13
// speedup vs baseline: 1.0132x; 1.0132x over previous
#include <cuda_runtime.h>
#include <cuda_bf16.h>
#include <cstdint>
#include <cstddef>

#define TT 1024
#define BB 64
#define DD 512
#define HH 512

// Recurrence partition: NI batch-groups (clusters) x NJ hidden-slices
#define NI 16
#define NJ 8
#define BSL (BB / NI)        // 4 batch rows per group
#define HSL (HH / NJ)        // 64 hidden units per slice
#define KC  4                // k-chunks of 128 per CTA
#define SLICE_BYTES (BSL * HSL * 4)
#define HS_BYTES (NJ * SLICE_BYTES)

// Device scratch (no cudaMalloc allowed)
__device__ float g_Z [(size_t)TT * BB * HH];
__device__ __nv_bfloat16 g_Ahi[(size_t)TT * BB * DD];
__device__ __nv_bfloat16 g_Alo[(size_t)TT * BB * DD];
__device__ __nv_bfloat16 g_Whi[(size_t)HH * DD];
__device__ __nv_bfloat16 g_Wlo[(size_t)HH * DD];

// ---------------------------------------------------------------------------
// PTX helpers
// ---------------------------------------------------------------------------
__device__ __forceinline__ uint32_t smem_u32(const void* p) {
    uint32_t a;
    asm("{ .reg .u64 t; cvta.to.shared.u64 t, %1; cvt.u32.u64 %0, t; }"
        : "=r"(a) : "l"(p));
    return a;
}
__device__ __forceinline__ uint32_t mapa_u32(uint32_t addr, uint32_t rank) {
    uint32_t r;
    asm("mapa.shared::cluster.u32 %0, %1, %2;" : "=r"(r) : "r"(addr), "r"(rank));
    return r;
}
__device__ __forceinline__ void mbar_init(uint32_t mbar, uint32_t cnt) {
    asm volatile("mbarrier.init.shared.b64 [%0], %1;" :: "r"(mbar), "r"(cnt) : "memory");
}
__device__ __forceinline__ void mbar_arrive_expect_tx(uint32_t mbar, uint32_t tx) {
    asm volatile("mbarrier.arrive.expect_tx.shared.b64 _, [%0], %1;"
                 :: "r"(mbar), "r"(tx) : "memory");
}
__device__ __forceinline__ void mbar_wait_parity(uint32_t mbar, uint32_t parity) {
    asm volatile(
        "{\n\t"
        ".reg .pred P;\n\t"
        "WAIT_%=:\n\t"
        "mbarrier.try_wait.parity.acquire.cta.shared::cta.b64 P, [%0], %1, 0x989680;\n\t"
        "@P bra.uni DONE_%=;\n\t"
        "bra.uni WAIT_%=;\n\t"
        "DONE_%=:\n\t"
        "}"
        :: "r"(mbar), "r"(parity) : "memory");
}
__device__ __forceinline__ void bulk_dsmem(uint32_t dst_cluster, uint32_t src_cta,
                                           uint32_t bytes, uint32_t mbar_cluster) {
    asm volatile(
        "cp.async.bulk.shared::cluster.shared::cta.mbarrier::complete_tx::bytes "
        "[%0], [%1], %2, [%3];"
        :: "r"(dst_cluster), "r"(src_cta), "r"(bytes), "r"(mbar_cluster) : "memory");
}
__device__ __forceinline__ void fence_proxy_async_cta() {
    asm volatile("fence.proxy.async.shared::cta;" ::: "memory");
}
__device__ __forceinline__ void ffma2(unsigned long long& d,
                                      unsigned long long a, unsigned long long b) {
    asm("fma.rn.f32x2 %0, %1, %2, %0;" : "+l"(d) : "l"(a), "l"(b));
}
__device__ __forceinline__ unsigned long long pack_f2(float lo, float hi) {
    return (unsigned long long)__float_as_uint(lo) |
           ((unsigned long long)__float_as_uint(hi) << 32);
}
__device__ __forceinline__ float lo_f(unsigned long long v) {
    return __uint_as_float((unsigned int)v);
}
__device__ __forceinline__ float hi_f(unsigned long long v) {
    return __uint_as_float((unsigned int)(v >> 32));
}

// mma.sync m16n8k16 bf16 (sm_80+ baseline PTX: safe at compute_103)
__device__ __forceinline__ void mma16816(float* d, const uint32_t* a, const uint32_t* b) {
    asm volatile(
        "mma.sync.aligned.m16n8k16.row.col.f32.bf16.bf16.f32 "
        "{%0,%1,%2,%3}, {%4,%5,%6,%7}, {%8,%9}, {%0,%1,%2,%3};"
        : "+f"(d[0]), "+f"(d[1]), "+f"(d[2]), "+f"(d[3])
        : "r"(a[0]), "r"(a[1]), "r"(a[2]), "r"(a[3]), "r"(b[0]), "r"(b[1]));
}
__device__ __forceinline__ void ldsm_x4(uint32_t* r, uint32_t addr) {
    asm volatile("ldmatrix.sync.aligned.m8n8.x4.shared.b16 {%0,%1,%2,%3}, [%4];"
        : "=r"(r[0]), "=r"(r[1]), "=r"(r[2]), "=r"(r[3]) : "r"(addr));
}
// cp.async 16B global->shared (LDGSTS)
__device__ __forceinline__ void cp_async16(uint32_t dst, const void* src) {
    asm volatile("cp.async.cg.shared.global [%0], [%1], 16;"
                 :: "r"(dst), "l"(src) : "memory");
}
__device__ __forceinline__ void cp_commit() {
    asm volatile("cp.async.commit_group;" ::: "memory");
}
__device__ __forceinline__ void cp_wait0() {
    asm volatile("cp.async.wait_group 0;" ::: "memory");
}

// ---------------------------------------------------------------------------
// Split-bf16 conversion (weights only)
// ---------------------------------------------------------------------------
__global__ void split_kernel(const float* __restrict__ src,
                             __nv_bfloat16* __restrict__ hi,
                             __nv_bfloat16* __restrict__ lo, int n)
{
    int idx = blockIdx.x * blockDim.x + threadIdx.x;
    int stride = gridDim.x * blockDim.x;
    for (int i = idx; i < n; i += stride) {
        float x = src[i];
        __nv_bfloat16 h = __float2bfloat16(x);
        hi[i] = h;
        lo[i] = __float2bfloat16(x - __bfloat162float(h));
    }
}

// ---------------------------------------------------------------------------
// HMMA GEMM v2: double-buffered SMEM + cp.async prefetch.
// C = (Ahi+Alo) @ (Whi+Wlo)^T + b1 + b2 (3-product split-bf16).
// If Af32 != nullptr, A is fp32: staged in registers, converted to hi/lo
// during the store phase (after compute, latency hidden).
// Tiles: [buf][tile][128][PAD] bf16; tile 0=Ah 1=Al 2=Wh 3=Wl.
// One cp.async.wait + one __syncthreads per 32-k block.
// ---------------------------------------------------------------------------
#define KB 32
#define PAD 40
#define NT (DD / KB)                 // 16
#define TILE_ELE (128 * PAD)         // 5120 bf16
#define BUF_ELE  (4 * TILE_ELE)      // 20480 bf16
#define GSMEM_BYTES (2 * BUF_ELE * 2)  // 81920 B

__global__ __launch_bounds__(256) void mma_gemm_kernel(
    const float* __restrict__ Af32,
    const __nv_bfloat16* __restrict__ Ahi, const __nv_bfloat16* __restrict__ Alo,
    const __nv_bfloat16* __restrict__ Whi, const __nv_bfloat16* __restrict__ Wlo,
    const float* __restrict__ b1, const float* __restrict__ b2,
    float* __restrict__ C)
{
    extern __shared__ __nv_bfloat16 sm[];

    const int tid   = threadIdx.x;
    const int wid   = tid >> 5;
    const int lane  = tid & 31;
    const int m0    = blockIdx.x * 128;
    const int n0    = blockIdx.y * 128;
    const int wm    = (wid >> 2) * 64;
    const int wn    = (wid & 3) * 32;

    float acc[4][4][4];
#pragma unroll
    for (int i = 0; i < 4; i++)
#pragma unroll
        for (int j = 0; j < 4; j++)
#pragma unroll
            for (int r = 0; r < 4; r++) acc[i][j][r] = 0.0f;

    const int ar = lane & 15, ac = (lane >> 4) * 8;
    const int br = (lane & 7) + ((lane >> 4) << 3), bc = ((lane >> 3) & 1) * 8;

    // Per-thread load coordinates (fixed across blocks)
    // bf16 tile loads: idx in [0,512): r = idx>>2, c = (idx&3)*8
    const int lr  = tid >> 2, lc = (tid & 3) * 8;
    const int lr1 = (tid + 256) >> 2, lc1 = ((tid + 256) & 3) * 8;
    // fp32 A loads: idx in [0,1024): r = idx>>3, c4 = (idx&7)*4
    float4 af[4];

    // Issue loads for block kb into buffer `buf`.
    auto issue_loads = [&](int kb, int buf) {
        const int k0 = kb * KB;
        __nv_bfloat16* base = sm + (size_t)buf * BUF_ELE;
        if (Af32) {
#pragma unroll
            for (int it = 0; it < 4; it++) {
                int idx = it * 256 + tid;
                int r = idx >> 3, c4 = (idx & 7) * 4;
                af[it] = *(const float4*)(Af32 + (size_t)(m0 + r) * DD + k0 + c4);
            }
        } else {
            __nv_bfloat16* dAh = base + 0 * TILE_ELE;
            __nv_bfloat16* dAl = base + 1 * TILE_ELE;
            cp_async16(smem_u32(dAh + lr  * PAD + lc ), Ahi + (size_t)(m0 + lr ) * DD + k0 + lc );
            cp_async16(smem_u32(dAh + lr1 * PAD + lc1), Ahi + (size_t)(m0 + lr1) * DD + k0 + lc1);
            cp_async16(smem_u32(dAl + lr  * PAD + lc ), Alo + (size_t)(m0 + lr ) * DD + k0 + lc );
            cp_async16(smem_u32(dAl + lr1 * PAD + lc1), Alo + (size_t)(m0 + lr1) * DD + k0 + lc1);
        }
        __nv_bfloat16* dWh = base + 2 * TILE_ELE;
        __nv_bfloat16* dWl = base + 3 * TILE_ELE;
        cp_async16(smem_u32(dWh + lr  * PAD + lc ), Whi + (size_t)(n0 + lr ) * DD + k0 + lc );
        cp_async16(smem_u32(dWh + lr1 * PAD + lc1), Whi + (size_t)(n0 + lr1) * DD + k0 + lc1);
        cp_async16(smem_u32(dWl + lr  * PAD + lc ), Wlo + (size_t)(n0 + lr ) * DD + k0 + lc );
        cp_async16(smem_u32(dWl + lr1 * PAD + lc1), Wlo + (size_t)(n0 + lr1) * DD + k0 + lc1);
        cp_commit();
    };

    // fp32-A path: convert staged registers into SMEM hi/lo tiles.
    auto finish_stores = [&](int buf) {
        if (!Af32) return;
        __nv_bfloat16* base = sm + (size_t)buf * BUF_ELE;
        __nv_bfloat16 (*dAh)[PAD] = (__nv_bfloat16(*)[PAD])(base + 0 * TILE_ELE);
        __nv_bfloat16 (*dAl)[PAD] = (__nv_bfloat16(*)[PAD])(base + 1 * TILE_ELE);
#pragma unroll
        for (int it = 0; it < 4; it++) {
            int idx = it * 256 + tid;
            int r = idx >> 3, c4 = (idx & 7) * 4;
            float4 v = af[it];
            __nv_bfloat16 hx = __float2bfloat16(v.x);
            __nv_bfloat16 hy = __float2bfloat16(v.y);
            __nv_bfloat16 hz = __float2bfloat16(v.z);
            __nv_bfloat16 hw = __float2bfloat16(v.w);
            *(__nv_bfloat162*)&dAh[r][c4]     = __nv_bfloat162(hx, hy);
            *(__nv_bfloat162*)&dAh[r][c4 + 2] = __nv_bfloat162(hz, hw);
            __nv_bfloat162 l0, l1;
            l0.x = __float2bfloat16(v.x - __bfloat162float(hx));
            l0.y = __float2bfloat16(v.y - __bfloat162float(hy));
            l1.x = __float2bfloat16(v.z - __bfloat162float(hz));
            l1.y = __float2bfloat16(v.w - __bfloat162float(hw));
            *(__nv_bfloat162*)&dAl[r][c4]     = l0;
            *(__nv_bfloat162*)&dAl[r][c4 + 2] = l1;
        }
    };

    // Prologue: block 0 into buffer 0
    issue_loads(0, 0);
    finish_stores(0);
    cp_wait0();
    __syncthreads();

    for (int kb = 0; kb < NT; kb++) {
        const int p = kb & 1;
        if (kb + 1 < NT) issue_loads(kb + 1, p ^ 1);

        __nv_bfloat16* base = sm + (size_t)p * BUF_ELE;
        __nv_bfloat16 (*sAh)[PAD] = (__nv_bfloat16(*)[PAD])(base + 0 * TILE_ELE);
        __nv_bfloat16 (*sAl)[PAD] = (__nv_bfloat16(*)[PAD])(base + 1 * TILE_ELE);
        __nv_bfloat16 (*sWh)[PAD] = (__nv_bfloat16(*)[PAD])(base + 2 * TILE_ELE);
        __nv_bfloat16 (*sWl)[PAD] = (__nv_bfloat16(*)[PAD])(base + 3 * TILE_ELE);

#pragma unroll
        for (int ks = 0; ks < 2; ks++) {
            const int kk = ks * 16;
            uint32_t fAh[4][4], fAl[4][4], fWh[2][4], fWl[2][4];
#pragma unroll
            for (int mf = 0; mf < 4; mf++) {
                ldsm_x4(fAh[mf], smem_u32(&sAh[wm + mf * 16 + ar][kk + ac]));
                ldsm_x4(fAl[mf], smem_u32(&sAl[wm + mf * 16 + ar][kk + ac]));
            }
#pragma unroll
            for (int np = 0; np < 2; np++) {
                ldsm_x4(fWh[np], smem_u32(&sWh[wn + np * 16 + br][kk + bc]));
                ldsm_x4(fWl[np], smem_u32(&sWl[wn + np * 16 + br][kk + bc]));
            }
#pragma unroll
            for (int mf = 0; mf < 4; mf++) {
#pragma unroll
                for (int np = 0; np < 2; np++) {
#pragma unroll
                    for (int h = 0; h < 2; h++) {
                        const int nf = np * 2 + h;
                        mma16816(acc[mf][nf], fAh[mf], &fWh[np][h * 2]);
                        mma16816(acc[mf][nf], fAh[mf], &fWl[np][h * 2]);
                        mma16816(acc[mf][nf], fAl[mf], &fWh[np][h * 2]);
                    }
                }
            }
        }

        if (kb + 1 < NT) {
            finish_stores(p ^ 1);
            cp_wait0();
            __syncthreads();
        }
    }

    const int erow = lane >> 2;
    const int ecol = (lane & 3) * 2;
#pragma unroll
    for (int mf = 0; mf < 4; mf++) {
#pragma unroll
        for (int nf = 0; nf < 4; nf++) {
            const int n = n0 + wn + nf * 8 + ecol;
            const float bv0 = __ldg(b1 + n)     + __ldg(b2 + n);
            const float bv1 = __ldg(b1 + n + 1) + __ldg(b2 + n + 1);
            const int r0 = m0 + wm + mf * 16 + erow;
            float2 o0 = make_float2(acc[mf][nf][0] + bv0, acc[mf][nf][1] + bv1);
            float2 o1 = make_float2(acc[mf][nf][2] + bv0, acc[mf][nf][3] + bv1);
            *(float2*)(C + (size_t)r0 * HH + n)       = o0;
            *(float2*)(C + (size_t)(r0 + 8) * HH + n) = o1;
        }
    }
}

// ---------------------------------------------------------------------------
// Persistent recurrence kernel (EXACT 6440-us R10 config: 256 threads,
// per-slice mbarriers, NPH=2, single chain, split-output epilogue).
// ---------------------------------------------------------------------------
__global__ __launch_bounds__(256, 1) __cluster_dims__(NJ, 1, 1)
void recur_kernel(
    const float* __restrict__ Z, const float* __restrict__ Whh,
    float* __restrict__ Yf,
    __nv_bfloat16* __restrict__ Yhi, __nv_bfloat16* __restrict__ Ylo)
{
    __shared__ float hs[2][NJ][BSL][HSL];        // 16 KB double-buffered h
    __shared__ float red[BSL][KC][HSL];          // 4 KB partial sums
    __shared__ float stage[2][BSL][HSL];         // 2 KB staging
    __shared__ alignas(8) unsigned long long mbar[2][NJ];

    const int j    = blockIdx.x;                 // hidden slice = cluster rank
    const int i    = blockIdx.y;                 // batch group
    const int tid  = threadIdx.x;
    const int kc   = tid >> 6;                   // warp-pair 0..3
    const int jloc = tid & 63;
    const int b0   = i * BSL;

    const uint32_t hs_base    = smem_u32(&hs[0][0][0][0]);
    const uint32_t mbar_base  = smem_u32(&mbar[0][0]);
    const uint32_t stage_base = smem_u32(&stage[0][0][0]);

    if (tid == 0) {
#pragma unroll
        for (int ph = 0; ph < 2; ph++)
#pragma unroll
            for (int s = 0; s < NJ; s++) {
                const uint32_t mb = mbar_base + (uint32_t)(ph * NJ + s) * 8;
                mbar_init(mb, 1);
                mbar_arrive_expect_tx(mb, SLICE_BYTES);
            }
    }
    asm volatile("barrier.cluster.arrive.aligned;" ::: "memory");
    asm volatile("barrier.cluster.wait.aligned;"  ::: "memory");

    uint32_t my_peer_hs = 0, my_peer_mb = 0;
    if (tid < NJ) {
        my_peer_hs = mapa_u32(hs_base,   (uint32_t)tid);
        my_peer_mb = mapa_u32(mbar_base, (uint32_t)tid);
    }

    // Whh chunk in registers as packed (even,odd) pairs
    unsigned long long w2[64];
    {
        const float* wrow = Whh + (size_t)(j * HSL + jloc) * HH + kc * 128;
#pragma unroll
        for (int q = 0; q < 32; q++) {
            float4 v = *(const float4*)(wrow + q * 4);
            w2[q * 2 + 0] = pack_f2(v.x, v.y);
            w2[q * 2 + 1] = pack_f2(v.z, v.w);
        }
    }

    const int rb  = tid >> 6;
    const int rjj = tid & 63;
    const int brow = b0 + rb;
    const int jg   = j * HSL + rjj;
    const size_t zy_off = (size_t)brow * HH + jg;

    const uint32_t mbA0 = mbar_base + (uint32_t)(0 * NJ + 2 * kc) * 8;
    const uint32_t mbA1 = mbar_base + (uint32_t)(1 * NJ + 2 * kc) * 8;

    int par[2] = {0, 0};

    for (int t = 0; t < TT; t++) {
        const int ph = t & 1;

        float zv = __ldcs(Z + (size_t)t * BB * HH + zy_off);

        float acc = 0.0f;
        if (t > 0) {
            const uint32_t mbA = (ph == 0) ? mbA0 : mbA1;   // slice 2kc
            const uint32_t mbB = mbA + 8;                    // slice 2kc+1
            const int p = par[ph];

            unsigned long long acc2[BSL];
#pragma unroll
            for (int b = 0; b < BSL; b++) acc2[b] = pack_f2(0.0f, 0.0f);

            // ---- slice 2kc ----
            mbar_wait_parity(mbA, p);
            {
                const int s = kc * 2;
#pragma unroll
                for (int b = 0; b < BSL; b++) {
                    const ulonglong2* hp = (const ulonglong2*)&hs[ph][s][b][0];
#pragma unroll
                    for (int q = 0; q < 16; q++) {
                        ulonglong2 hv = hp[q];
                        ffma2(acc2[b], hv.x, w2[q * 2 + 0]);
                        ffma2(acc2[b], hv.y, w2[q * 2 + 1]);
                    }
                }
            }
            // ---- slice 2kc+1 ----
            mbar_wait_parity(mbB, p);
            if (jloc == 0) {
                mbar_arrive_expect_tx(mbA, SLICE_BYTES);
                mbar_arrive_expect_tx(mbB, SLICE_BYTES);
            }
            {
                const int s = kc * 2 + 1;
#pragma unroll
                for (int b = 0; b < BSL; b++) {
                    const ulonglong2* hp = (const ulonglong2*)&hs[ph][s][b][0];
#pragma unroll
                    for (int q = 0; q < 16; q++) {
                        ulonglong2 hv = hp[q];
                        ffma2(acc2[b], hv.x, w2[32 + q * 2 + 0]);
                        ffma2(acc2[b], hv.y, w2[32 + q * 2 + 1]);
                    }
                }
            }
            par[ph] = p ^ 1;

#pragma unroll
            for (int b = 0; b < BSL; b++)
                red[b][kc][jloc] = lo_f(acc2[b]) + hi_f(acc2[b]);
            __syncthreads();

#pragma unroll
            for (int c = 0; c < KC; c++) acc += red[rb][c][rjj];
        }

        float val = tanhf(acc + zv);
        const size_t go = (size_t)t * BB * HH + zy_off;
        if (Yhi) {
            __nv_bfloat16 h = __float2bfloat16(val);
            Yhi[go] = h;
            Ylo[go] = __float2bfloat16(val - __bfloat162float(h));
        } else {
            Yf[go] = val;
        }

        if (t + 1 < TT) {
            const int sph = t & 1;
            stage[sph][rb][rjj] = val;
            __syncthreads();
            if (tid < NJ) {
                fence_proxy_async_cta();
                const uint32_t src = stage_base + (uint32_t)sph * SLICE_BYTES;
                const uint32_t dst = my_peer_hs
                    + (uint32_t)(ph ^ 1) * HS_BYTES + (uint32_t)j * SLICE_BYTES;
                const uint32_t mb  = my_peer_mb + (uint32_t)((ph ^ 1) * NJ + j) * 8;
                bulk_dsmem(dst, src, SLICE_BYTES, mb);
            }
        } else {
            __syncthreads();
        }
    }

    asm volatile("barrier.cluster.arrive.aligned;" ::: "memory");
    asm volatile("barrier.cluster.wait.aligned;"  ::: "memory");
}

// ---------------------------------------------------------------------------
extern "C" void kernel_launch(void* const* d_in, const int* in_sizes, int n_in,
                              void* d_out, int out_size)
{
    const float* Xt   = (const float*)d_in[0];
    const float* ihW0 = (const float*)d_in[1];
    const float* ihB0 = (const float*)d_in[2];
    const float* hhW0 = (const float*)d_in[3];
    const float* hhB0 = (const float*)d_in[4];
    const float* ihW1 = (const float*)d_in[5];
    const float* ihB1 = (const float*)d_in[6];
    const float* hhW1 = (const float*)d_in[7];
    const float* hhB1 = (const float*)d_in[8];
    float* out = (float*)d_out;

    float *zp = nullptr;
    __nv_bfloat16 *ahi, *alo, *whi, *wlo;
    cudaGetSymbolAddress((void**)&zp,  g_Z);
    cudaGetSymbolAddress((void**)&ahi, g_Ahi);
    cudaGetSymbolAddress((void**)&alo, g_Alo);
    cudaGetSymbolAddress((void**)&whi, g_Whi);
    cudaGetSymbolAddress((void**)&wlo, g_Wlo);

    cudaFuncSetAttribute(mma_gemm_kernel,
                         cudaFuncAttributeMaxDynamicSharedMemorySize, GSMEM_BYTES);

    dim3 ggrid(TT * BB / 128, HH / 128);   // (512, 4)
    dim3 rgrid(NJ, NI);                    // (8, 16)

    const int NW = HH * DD;

    // ---- Layer 0 ----
    split_kernel<<<512, 256>>>(ihW0, whi, wlo, NW);
    mma_gemm_kernel<<<ggrid, 256, GSMEM_BYTES>>>(Xt, nullptr, nullptr, whi, wlo,
                                                 ihB0, hhB0, zp);
    recur_kernel<<<rgrid, 256>>>(zp, hhW0, nullptr, ahi, alo);

    // ---- Layer 1 ----
    split_kernel<<<512, 256>>>(ihW1, whi, wlo, NW);
    mma_gemm_kernel<<<ggrid, 256, GSMEM_BYTES>>>(nullptr, ahi, alo, whi, wlo,
                                                 ihB1, hhB1, zp);
    recur_kernel<<<rgrid, 256>>>(zp, hhW1, out, nullptr, nullptr);
}